// round 6
// baseline (speedup 1.0000x reference)
#include <cuda_runtime.h>

#define NCTA 128
#define NTHR 512
#define TSTEPS 512
#define Bb 64
#define Hh 1024
#define K2H 2048

typedef unsigned long long u64_t;

// Persistent device state. All transposed: [col][row], row=batch.
__device__ float g_sT[9][Hh * Bb];
__device__ float g_hT[Hh * Bb];
__device__ float g_embT[Hh * Bb];
__device__ unsigned g_flags[NCTA];   // per-CTA barrier flags (monotonic epochs)

// ---- packed f32x2 (Blackwell) ----
__device__ __forceinline__ u64_t pack2(float lo, float hi) {
    u64_t r; asm("mov.b64 %0, {%1, %2};" : "=l"(r) : "f"(lo), "f"(hi)); return r;
}
__device__ __forceinline__ void fma2(u64_t& d, u64_t a, u64_t b) {
    asm("fma.rn.f32x2 %0, %1, %2, %3;" : "=l"(d) : "l"(a), "l"(b), "l"(d));
}
__device__ __forceinline__ u64_t add2(u64_t a, u64_t b) {
    u64_t d; asm("add.rn.f32x2 %0, %1, %2;" : "=l"(d) : "l"(a), "l"(b)); return d;
}
__device__ __forceinline__ u64_t ldcg_u64(const float* p) {
    u64_t v; asm volatile("ld.global.cg.b64 %0, [%1];" : "=l"(v) : "l"(p)); return v;
}
__device__ __forceinline__ float4 ldcg_f4(const float* p) {
    float4 v;
    asm volatile("ld.global.cg.v4.f32 {%0,%1,%2,%3}, [%4];"
                 : "=f"(v.x), "=f"(v.y), "=f"(v.z), "=f"(v.w) : "l"(p));
    return v;
}
__device__ __forceinline__ float ldcg_f(const float* p) {
    float v; asm volatile("ld.global.cg.f32 %0, [%1];" : "=f"(v) : "l"(p)); return v;
}

__device__ __forceinline__ float sigm(float x) { return 1.f / (1.f + expf(-x)); }
__device__ __forceinline__ float actf(int code, float x) {
    switch (code) {
        case 0:  return tanhf(x);
        case 1:  return fmaxf(x, 0.f);
        case 2:  return sigm(x);
        default: return x;
    }
}

// Flag-array grid barrier: parallel per-CTA flag stores, 128 pollers.
// Mutable state is always read via ld.cg (L2), so no L1-invalidate needed.
__device__ __forceinline__ void grid_sync(unsigned e) {
    __threadfence();            // make this thread's STGs device-visible
    __syncthreads();            // all threads' fences done
    if (threadIdx.x == 0)
        *((volatile unsigned*)&g_flags[blockIdx.x]) = e;
    if (threadIdx.x < NCTA) {
        while (*((volatile unsigned*)&g_flags[threadIdx.x]) < e) { }
    }
    __syncthreads();
}

// One 8-col x 64-row output tile: out = gated(Sin); pre-act = x @ W (W:[K][2048], c|h halves).
// x transposed [k][64]; k<Ka from xA else xB (warp k-slices never straddle Ka).
// 16 warps split K; software-pipelined inner loop; two-stage smem reduction.
__device__ __noinline__ void gemm_tile(
    const float* __restrict__ W, const float* __restrict__ xA,
    const float* __restrict__ xB, int Ka, int K,
    const float* __restrict__ gateT, float* __restrict__ outT,
    int j0, int act, u64_t* red)
{
    const int lane = threadIdx.x & 31;
    const int warp = threadIdx.x >> 5;
    const int ct = lane & 1;           // 2 col-threads: 4 cols each
    const int g  = lane >> 1;          // 16 row-groups: 4 rows each
    const int colbase = j0 + ct * 4;
    const int rowbase = g * 4;
    const int kslice = K >> 4;         // 16-way K split
    const int kbeg = warp * kslice;

    const float* xp = ((kbeg < Ka) ? (xA + (size_t)kbeg * Bb)
                                   : (xB + (size_t)(kbeg - Ka) * Bb)) + rowbase;
    const float* wp = W + (size_t)kbeg * K2H + colbase;

    u64_t acc[4][2][2];                // [row r][colpair cp][half h]
    #pragma unroll
    for (int r = 0; r < 4; r++)
        #pragma unroll
        for (int cp = 0; cp < 2; cp++) { acc[r][cp][0] = 0ull; acc[r][cp][1] = 0ull; }

    // software pipeline: prefetch distance 1, unroll 4 lets ptxas rotate deeper
    float4 xv = ldcg_f4(xp);
    u64_t wA = *(const u64_t*)(wp);
    u64_t wB = *(const u64_t*)(wp + 2);
    u64_t wC = *(const u64_t*)(wp + Hh);
    u64_t wD = *(const u64_t*)(wp + Hh + 2);

    #pragma unroll 4
    for (int k = 0; k < kslice - 1; k++) {
        xp += Bb; wp += K2H;
        float4 xn = ldcg_f4(xp);
        u64_t nA = *(const u64_t*)(wp);
        u64_t nB = *(const u64_t*)(wp + 2);
        u64_t nC = *(const u64_t*)(wp + Hh);
        u64_t nD = *(const u64_t*)(wp + Hh + 2);

        u64_t xb;
        xb = pack2(xv.x, xv.x);
        fma2(acc[0][0][0], xb, wA); fma2(acc[0][1][0], xb, wB);
        fma2(acc[0][0][1], xb, wC); fma2(acc[0][1][1], xb, wD);
        xb = pack2(xv.y, xv.y);
        fma2(acc[1][0][0], xb, wA); fma2(acc[1][1][0], xb, wB);
        fma2(acc[1][0][1], xb, wC); fma2(acc[1][1][1], xb, wD);
        xb = pack2(xv.z, xv.z);
        fma2(acc[2][0][0], xb, wA); fma2(acc[2][1][0], xb, wB);
        fma2(acc[2][0][1], xb, wC); fma2(acc[2][1][1], xb, wD);
        xb = pack2(xv.w, xv.w);
        fma2(acc[3][0][0], xb, wA); fma2(acc[3][1][0], xb, wB);
        fma2(acc[3][0][1], xb, wC); fma2(acc[3][1][1], xb, wD);

        xv = xn; wA = nA; wB = nB; wC = nC; wD = nD;
    }
    {
        u64_t xb;
        xb = pack2(xv.x, xv.x);
        fma2(acc[0][0][0], xb, wA); fma2(acc[0][1][0], xb, wB);
        fma2(acc[0][0][1], xb, wC); fma2(acc[0][1][1], xb, wD);
        xb = pack2(xv.y, xv.y);
        fma2(acc[1][0][0], xb, wA); fma2(acc[1][1][0], xb, wB);
        fma2(acc[1][0][1], xb, wC); fma2(acc[1][1][1], xb, wD);
        xb = pack2(xv.z, xv.z);
        fma2(acc[2][0][0], xb, wA); fma2(acc[2][1][0], xb, wB);
        fma2(acc[2][0][1], xb, wC); fma2(acc[2][1][1], xb, wD);
        xb = pack2(xv.w, xv.w);
        fma2(acc[3][0][0], xb, wA); fma2(acc[3][1][0], xb, wB);
        fma2(acc[3][0][1], xb, wC); fma2(acc[3][1][1], xb, wD);
    }

    // Stage 1: warps 8..15 store partials into slot (warp-8).
    if (warp >= 8) {
        u64_t* my = red + ((size_t)((warp - 8) * 32 + lane)) * 16;
        #pragma unroll
        for (int r = 0; r < 4; r++)
            #pragma unroll
            for (int cp = 0; cp < 2; cp++) {
                my[(r * 4 + cp * 2) + 0] = acc[r][cp][0];
                my[(r * 4 + cp * 2) + 1] = acc[r][cp][1];
            }
    }
    __syncthreads();

    // Stage 2: warps 0..7 add partner partials into slot warp.
    if (warp < 8) {
        u64_t* my = red + ((size_t)(warp * 32 + lane)) * 16;
        #pragma unroll
        for (int r = 0; r < 4; r++)
            #pragma unroll
            for (int cp = 0; cp < 2; cp++) {
                int i0 = r * 4 + cp * 2;
                my[i0 + 0] = add2(my[i0 + 0], acc[r][cp][0]);
                my[i0 + 1] = add2(my[i0 + 1], acc[r][cp][1]);
            }
    }
    __syncthreads();

    // Stage 3: 512 threads finalize 512 outputs (8 cols x 64 rows).
    {
        const int t   = threadIdx.x;
        const int c8  = t & 7;
        const int row = t >> 3;
        const int sct = c8 >> 2;
        const int cp  = (c8 >> 1) & 1;
        const int par = c8 & 1;
        const int sg  = row >> 2;
        const int r   = row & 3;
        const int slane = sg * 2 + sct;
        const float* redf = (const float*)red;
        const int fbase = slane * 32 + (r * 4 + cp * 2) * 2 + par;

        float sc = 0.f, sh = 0.f;
        #pragma unroll
        for (int s = 0; s < 8; s++) {
            const float* rp = redf + (size_t)s * 32 * 32 + fbase;
            sc += rp[0];
            sh += rp[2];
        }
        const int col = j0 + c8;
        const size_t o = (size_t)col * Bb + row;
        float sp = ldcg_f(gateT + o);
        float cv = sigm(sc);
        float hv = actf(act, sh);
        outT[o] = sp + cv * (hv - sp);
    }
    __syncthreads();
}

__global__ __launch_bounds__(NTHR, 1) void darts_persistent_kernel(
    const int* __restrict__ X, const float* __restrict__ hidden,
    const float* __restrict__ emb, const float* __restrict__ W0,
    const float* __restrict__ Ws, const float* __restrict__ Wout,
    const float* __restrict__ bout, float* __restrict__ out, int out_size)
{
    __shared__ u64_t red[8 * 32 * 16];   // 32 KB two-stage reduction buffer
    const int cta = blockIdx.x;
    const int tid = threadIdx.x;
    unsigned epoch = *((volatile unsigned*)&g_flags[cta]);  // all equal at launch entry

    // init: transposed hidden and embT for t=0
    {
        int idx = cta * 512 + tid;
        int k = idx >> 6, row = idx & 63;
        g_hT[idx] = hidden[(size_t)row * Hh + k];
        int tok = __ldg(&X[row]);
        g_embT[idx] = __ldg(&emb[(size_t)tok * Hh + k]);
    }
    grid_sync(++epoch);

    const size_t WSZ = (size_t)Hh * K2H;
    const int j0 = cta * 8;

    for (int t = 0; t < TSTEPS; t++) {
        // L0: s0 from [emb ; h] @ W0, gate base = h, act tanh
        gemm_tile(W0, g_embT, g_hT, Hh, K2H, g_hT, g_sT[0], j0, 0, red);
        grid_sync(++epoch);

        // L1: s1 = node0(s0), sigmoid
        gemm_tile(Ws + 0 * WSZ, g_sT[0], g_sT[0], Hh, Hh, g_sT[0], g_sT[1], j0, 2, red);
        grid_sync(++epoch);

        // L2: s2 = node1(s1) relu, s3 = node2(s1) relu, s4 = node3(s1) identity
        gemm_tile(Ws + 1 * WSZ, g_sT[1], g_sT[1], Hh, Hh, g_sT[1], g_sT[2], j0, 1, red);
        gemm_tile(Ws + 2 * WSZ, g_sT[1], g_sT[1], Hh, Hh, g_sT[1], g_sT[3], j0, 1, red);
        gemm_tile(Ws + 3 * WSZ, g_sT[1], g_sT[1], Hh, Hh, g_sT[1], g_sT[4], j0, 3, red);
        grid_sync(++epoch);

        // L3: s5 = node4(s2), tanh
        gemm_tile(Ws + 4 * WSZ, g_sT[2], g_sT[2], Hh, Hh, g_sT[2], g_sT[5], j0, 0, red);
        grid_sync(++epoch);

        // L4: s7 = node6(s3) tanh, s6 = node5(s5) sigmoid, s8 = node7(s5) relu
        gemm_tile(Ws + 6 * WSZ, g_sT[3], g_sT[3], Hh, Hh, g_sT[3], g_sT[7], j0, 0, red);
        gemm_tile(Ws + 5 * WSZ, g_sT[5], g_sT[5], Hh, Hh, g_sT[5], g_sT[6], j0, 2, red);
        gemm_tile(Ws + 7 * WSZ, g_sT[5], g_sT[5], Hh, Hh, g_sT[5], g_sT[8], j0, 1, red);

        // fused combine (own cols; s6/s7/s8 written by this CTA, visible after
        // gemm_tile's trailing __syncthreads) + embT gather for t+1
        {
            int idx = cta * 512 + tid;
            float s = 0.f;
            #pragma unroll
            for (int n = 1; n <= 8; n++) s += ldcg_f(&g_sT[n][idx]);
            g_hT[idx] = s * 0.125f;
            if (t + 1 < TSTEPS) {
                int k = idx >> 6, row = idx & 63;
                int tok = __ldg(&X[(t + 1) * Bb + row]);
                g_embT[idx] = __ldg(&emb[(size_t)tok * Hh + k]);
            }
        }
        grid_sync(++epoch);
    }

    // head: a_hat = h @ W_out + b_out; probs = softmax (4-wide, lane-aligned groups)
    if (cta == 0 && tid < 256) {
        int b = tid >> 2, o = tid & 3;
        float acc = 0.f;
        for (int k = 0; k < Hh; k++) acc += ldcg_f(&g_hT[(size_t)k * Bb + b]) * Wout[k * 4 + o];
        acc += bout[o];
        float m = acc;
        m = fmaxf(m, __shfl_xor_sync(0xFFFFFFFFu, m, 1));
        m = fmaxf(m, __shfl_xor_sync(0xFFFFFFFFu, m, 2));
        float e = expf(acc - m);
        float ssum = e;
        ssum += __shfl_xor_sync(0xFFFFFFFFu, ssum, 1);
        ssum += __shfl_xor_sync(0xFFFFFFFFu, ssum, 2);
        out[b * 4 + o] = acc;
        if (out_size >= 512) out[256 + b * 4 + o] = e / ssum;
    }
}

extern "C" void kernel_launch(void* const* d_in, const int* in_sizes, int n_in,
                              void* d_out, int out_size) {
    const int*   X      = (const int*)d_in[0];
    const float* hidden = (const float*)d_in[1];
    const float* emb    = (const float*)d_in[2];
    const float* W0     = (const float*)d_in[3];
    const float* Ws     = (const float*)d_in[4];
    const float* W_out  = (const float*)d_in[5];
    const float* b_out  = (const float*)d_in[6];
    (void)in_sizes; (void)n_in;

    darts_persistent_kernel<<<NCTA, NTHR>>>(X, hidden, emb, W0, Ws, W_out, b_out,
                                            (float*)d_out, out_size);
}